// round 8
// baseline (speedup 1.0000x reference)
#include <cuda_runtime.h>
#include <cuda_fp16.h>
#include <math.h>
#include <stdint.h>

#define B_ 8
#define N_ 2048
#define D_ 256

// ---------------------------------------------------------------------------
// helpers (baseline PTX only: cp.async / ldmatrix / mma.sync — compute_100 OK)
// ---------------------------------------------------------------------------
__device__ __forceinline__ unsigned smem_u32(const void* p) {
    unsigned a;
    asm("{ .reg .u64 t; cvta.to.shared.u64 t, %1; cvt.u32.u64 %0, t; }"
        : "=r"(a) : "l"(p));
    return a;
}
__device__ __forceinline__ int SWZ(int x) { return x ^ ((x >> 3) & 0x70); }

#define CP16(dst, src) \
    asm volatile("cp.async.cg.shared.global [%0], [%1], 16;" \
                 :: "r"((unsigned)(dst)), "l"(__cvta_generic_to_global(src)) : "memory")
#define CPC() asm volatile("cp.async.commit_group;" ::: "memory")
#define CPW0() asm volatile("cp.async.wait_group 0;" ::: "memory")
#define CPW1() asm volatile("cp.async.wait_group 1;" ::: "memory")

#define LDSM4(r0, r1, r2, r3, a) \
    asm volatile("ldmatrix.sync.aligned.m8n8.x4.shared.b16 {%0,%1,%2,%3}, [%4];" \
                 : "=r"(r0), "=r"(r1), "=r"(r2), "=r"(r3) : "r"((unsigned)(a)))

#define MMA(d, a0, a1, a2, a3, b0, b1) \
    asm volatile("mma.sync.aligned.m16n8k16.row.col.f32.f16.f16.f32 " \
                 "{%0,%1,%2,%3}, {%4,%5,%6,%7}, {%8,%9}, {%0,%1,%2,%3};" \
                 : "+f"((d)[0]), "+f"((d)[1]), "+f"((d)[2]), "+f"((d)[3]) \
                 : "r"(a0), "r"(a1), "r"(a2), "r"(a3), "r"(b0), "r"(b1))

// ---------------------------------------------------------------------------
// device globals (no allocation allowed)
// ---------------------------------------------------------------------------
__device__ float g_wl[D_];
__device__ float g_wr[D_];
__device__ __align__(16) float2 g_Elp[B_ * N_];   // (exp(hl), exp(0.2 hl))
__device__ __align__(16) float2 g_Erp[B_ * N_];   // (exp(hr), exp(0.2 hr))
__device__ __align__(16) __half g_Whf[D_ * D_];            // W fp16 row-major [o][k]
__device__ __align__(16) __half g_xh [B_ * N_ * D_];       // x fp16 row-major [m][k]
__device__ __align__(128) unsigned char g_ht[B_ * 32 * 32768]; // h^T fp16: [b][jt][d 256][j 64] swizzled

// ---------------- k_wlr: wl/wr vectors (1 block) ----------------------------
__global__ void k_wlr(const float* __restrict__ W, const float* __restrict__ a)
{
    int d = threadIdx.x;                      // 256 threads
    float sl = 0.f, sr = 0.f;
    #pragma unroll 8
    for (int o = 0; o < D_; ++o) {
        float w = W[o * D_ + d];
        sl = fmaf(a[o],      w, sl);
        sr = fmaf(a[D_ + o], w, sr);
    }
    g_wl[d] = sl;
    g_wr[d] = sr;
}

// ---------------- k_wconv: W f32 -> fp16, 16 blocks -------------------------
__global__ void k_wconv(const float* __restrict__ W)
{
    int i = blockIdx.x * 256 + threadIdx.x;   // 4096 threads, 16 f32 each
    const float4* W4 = (const float4*)W;
    __half2* o = (__half2*)g_Whf;
    #pragma unroll
    for (int q = 0; q < 4; ++q) {
        float4 v = W4[i * 4 + q];
        o[i * 8 + q * 2]     = __floats2half2_rn(v.x, v.y);
        o[i * 8 + q * 2 + 1] = __floats2half2_rn(v.z, v.w);
    }
}

// ---------------- k_hlr: hl/hr dots + factored exps + x->fp16 side-write ----
__global__ void k_hlr(const float* __restrict__ x)
{
    int m    = blockIdx.x * 8 + (threadIdx.x >> 5);
    int lane = threadIdx.x & 31;
    const float4* xr  = (const float4*)(x + (size_t)m * D_);
    const float4* wl4 = (const float4*)g_wl;
    const float4* wr4 = (const float4*)g_wr;
    float sl = 0.f, sr = 0.f;
    __half2* xo = (__half2*)(g_xh + (size_t)m * D_);
    #pragma unroll
    for (int q = 0; q < 2; ++q) {
        float4 xv = xr [lane + q * 32];
        float4 lv = wl4[lane + q * 32];
        float4 rv = wr4[lane + q * 32];
        sl += xv.x * lv.x + xv.y * lv.y + xv.z * lv.z + xv.w * lv.w;
        sr += xv.x * rv.x + xv.y * rv.y + xv.z * rv.z + xv.w * rv.w;
        xo[(lane + q * 32) * 2]     = __floats2half2_rn(xv.x, xv.y);
        xo[(lane + q * 32) * 2 + 1] = __floats2half2_rn(xv.z, xv.w);
    }
    #pragma unroll
    for (int off = 16; off > 0; off >>= 1) {
        sl += __shfl_xor_sync(0xFFFFFFFFu, sl, off);
        sr += __shfl_xor_sync(0xFFFFFFFFu, sr, off);
    }
    if (lane == 0) {
        g_Elp[m] = make_float2(expf(sl), expf(0.2f * sl));
        g_Erp[m] = make_float2(expf(sr), expf(0.2f * sr));
    }
}

// ---------------------------------------------------------------------------
// k_xh: h^T[d][j] = sum_k W[d][k] x[j][k]  (HMMA), smem-staged coalesced out
// CTA: 64 d x 256 j; warps m32 x n64; K loop 4 chunks of 64; 2 CTAs/SM
// ---------------------------------------------------------------------------
__global__ __launch_bounds__(256, 2) void k_xh()
{
    extern __shared__ char sm[];
    const int WS = 0, XS = 32768;
    unsigned sb = smem_u32(sm);
    int t = threadIdx.x, l = t & 31, w = t >> 5;
    int wm = w & 1, wn = w >> 1;
    int j0 = blockIdx.x * 256;
    int d0 = blockIdx.y * 64;

    #pragma unroll
    for (int q = 0; q < 8; ++q) {
        int idx = t + q * 256;
        int kc = idx >> 9, r = (idx >> 3) & 63, ch = idx & 7;
        CP16(sb + WS + kc * 8192 + SWZ(r * 128 + ch * 16),
             (const char*)g_Whf + (size_t)(d0 + r) * 512 + kc * 128 + ch * 16);
    }
    #pragma unroll
    for (int q = 0; q < 8; ++q) {
        int idx = t + q * 256, r = idx >> 3, ch = idx & 7;
        CP16(sb + XS + SWZ(r * 128 + ch * 16),
             (const char*)g_xh + (size_t)(j0 + r) * 512 + ch * 16);
    }
    CPC();

    float acc[8][2][4];
    #pragma unroll
    for (int i = 0; i < 8; ++i)
        #pragma unroll
        for (int m = 0; m < 2; ++m)
            #pragma unroll
            for (int c = 0; c < 4; ++c) acc[i][m][c] = 0.f;

    for (int kc = 0; kc < 4; ++kc) {
        if (kc < 3) {
            unsigned bbuf = sb + XS + ((kc + 1) & 1) * 32768;
            #pragma unroll
            for (int q = 0; q < 8; ++q) {
                int idx = t + q * 256, r = idx >> 3, ch = idx & 7;
                CP16(bbuf + SWZ(r * 128 + ch * 16),
                     (const char*)g_xh + (size_t)(j0 + r) * 512 + (kc + 1) * 128 + ch * 16);
            }
            CPC();
            CPW1();
        } else {
            CPW0();
        }
        __syncthreads();

        unsigned ab = sb + WS + kc * 8192;
        unsigned bb = sb + XS + (kc & 1) * 32768;
        #pragma unroll
        for (int ks = 0; ks < 4; ++ks) {
            unsigned a0[4], a1[4];
            LDSM4(a0[0], a0[1], a0[2], a0[3],
                  ab + SWZ((wm * 32      + (l & 15)) * 128 + ks * 32 + (l >> 4) * 16));
            LDSM4(a1[0], a1[1], a1[2], a1[3],
                  ab + SWZ((wm * 32 + 16 + (l & 15)) * 128 + ks * 32 + (l >> 4) * 16));
            #pragma unroll
            for (int nb2 = 0; nb2 < 4; ++nb2) {
                unsigned b0, b1, b2, b3;
                LDSM4(b0, b1, b2, b3,
                      bb + SWZ((wn * 64 + nb2 * 16 + (l & 15)) * 128 + ks * 32 + (l >> 4) * 16));
                MMA(acc[2*nb2][0],   a0[0], a0[1], a0[2], a0[3], b0, b2);
                MMA(acc[2*nb2][1],   a1[0], a1[1], a1[2], a1[3], b0, b2);
                MMA(acc[2*nb2+1][0], a0[0], a0[1], a0[2], a0[3], b1, b3);
                MMA(acc[2*nb2+1][1], a1[0], a1[1], a1[2], a1[3], b1, b3);
            }
        }
        __syncthreads();
    }

    // stage output (fp16, swizzled tile image) into smem, then coalesced copy
    #pragma unroll
    for (int mi = 0; mi < 2; ++mi) {
        int rd = wm * 32 + mi * 16 + (l >> 2);
        #pragma unroll
        for (int nb = 0; nb < 8; ++nb) {
            int jj = nb * 8 + 2 * (l & 3);
            __half2 v0 = __floats2half2_rn(acc[nb][mi][0], acc[nb][mi][1]);
            __half2 v1 = __floats2half2_rn(acc[nb][mi][2], acc[nb][mi][3]);
            *(__half2*)(sm + WS + wn * 8192 + SWZ( rd      * 128 + jj * 2)) = v0;
            *(__half2*)(sm + WS + wn * 8192 + SWZ((rd + 8) * 128 + jj * 2)) = v1;
        }
    }
    __syncthreads();

    int b   = j0 >> 11;
    int jt0 = (j0 & 2047) >> 6;
    #pragma unroll
    for (int q = 0; q < 8; ++q) {
        int c  = t + q * 256;                 // 2048 chunks x 16B
        int jt = c >> 9;
        int off = (c & 511) * 16;
        unsigned char* dst = g_ht + (size_t)(b * 32 + jt0 + jt) * 32768 + d0 * 128 + off;
        *(uint4*)dst = *(const uint4*)(sm + WS + c * 16);
    }
}

// ---------------------------------------------------------------------------
// k_aggr: fused masked-softmax aggregation (HMMA)
// - adj: register-resident LDG pipeline (no smem round trip)
// - H: 3-buffer cp.async, prefetch distance 2
// - row sums: fp32 accumulation in P-phase (no ones-MMA)
// CTA 512 thr, i-tile M=128, warp tile m32 x n64 (wm, wn in 0..3), 32 j-tiles
// smem: H 3x32KB @0 | P 2x16KB @98304 | ER 16KB @131072 | ELP 1KB @147456
//       | RSUM 512B @148480  (total 148992)
// ---------------------------------------------------------------------------
__global__ __launch_bounds__(512) void k_aggr(const int* __restrict__ adj,
                                              float* __restrict__ out)
{
    extern __shared__ char sm[];
    const int HS = 0, PS = 98304, ERS = 131072, ELP = 147456, RSUM = 148480;
    unsigned sb = smem_u32(sm);
    int t = threadIdx.x, l = t & 31, w = t >> 5;
    int wm = w & 3, wn = w >> 2;
    int b = blockIdx.y, i0 = blockIdx.x * 128;
    float2* elp  = (float2*)(sm + ELP);
    float*  rsum = (float*)(sm + RSUM);

    const unsigned char* hsrc = g_ht + (size_t)b * 32 * 32768;
    const int*           adjb = adj + ((size_t)b * N_ + i0) * N_;

    // thread's P rows: r0 = t>>3 (rep0), r0+64 (rep1); 8 j-cols chunk c8 = t&7
    int r0 = t >> 3, c8 = t & 7;
    const int* aj0 = adjb + (size_t)r0 * N_ + c8 * 8;          // rep0 base
    const int* aj1 = adjb + (size_t)(r0 + 64) * N_ + c8 * 8;   // rep1 base

    // prologue: group0 = H(0)+Er+Elp; group1 = H(1); LDG adj(0)
    #pragma unroll
    for (int q = 0; q < 4; ++q) {
        int idx = t + q * 512;
        CP16(sb + HS + idx * 16, hsrc + idx * 16);
    }
    #pragma unroll
    for (int q = 0; q < 2; ++q) {
        int idx = t + q * 512;
        CP16(sb + ERS + idx * 16, (const char*)(g_Erp + b * N_) + idx * 16);
    }
    if (t < 64) CP16(sb + ELP + t * 16, (const char*)(g_Elp + b * N_ + i0) + t * 16);
    CPC();
    #pragma unroll
    for (int q = 0; q < 4; ++q) {
        int idx = t + q * 512;
        CP16(sb + HS + 32768 + idx * 16, hsrc + 32768 + idx * 16);
    }
    CPC();

    int4 av[2][2];
    av[0][0] = *(const int4*)(aj0);     av[0][1] = *(const int4*)(aj0 + 4);
    av[1][0] = *(const int4*)(aj1);     av[1][1] = *(const int4*)(aj1 + 4);

    CPW1();                 // group0 (H0+Er+Elp) arrived; H1 in flight
    __syncthreads();

    float rp0 = 0.f, rp1 = 0.f;       // running row sums (rows r0, r0+64)
    const float4* er4 = (const float4*)(sm + ERS);
    float2 el0 = elp[r0], el1 = elp[r0 + 64];

    // P(nt) from registers; writes P buffer nt&1; accumulates rp
    #define P_PHASE(nt) do {                                                   \
        char* pb = sm + PS + ((nt) & 1) * 16384;                               \
        _Pragma("unroll")                                                      \
        for (int rep = 0; rep < 2; ++rep) {                                    \
            float2 el = rep ? el1 : el0;                                       \
            int row = rep ? (r0 + 64) : r0;                                    \
            uint4 pk;                                                          \
            float rs = 0.f;                                                    \
            _Pragma("unroll")                                                  \
            for (int g = 0; g < 2; ++g) {                                      \
                int4 a4 = av[rep][g];                                          \
                float4 ea = er4[(nt) * 32 + c8 * 4 + g * 2];                   \
                float4 eb = er4[(nt) * 32 + c8 * 4 + g * 2 + 1];               \
                float q0 = el.x * ea.x; float p0 = (q0 > 1.f) ? q0 : el.y * ea.y; \
                float q1 = el.x * ea.z; float p1 = (q1 > 1.f) ? q1 : el.y * ea.w; \
                float q2 = el.x * eb.x; float p2 = (q2 > 1.f) ? q2 : el.y * eb.y; \
                float q3 = el.x * eb.z; float p3 = (q3 > 1.f) ? q3 : el.y * eb.w; \
                p0 = a4.x ? p0 : 0.f;  p1 = a4.y ? p1 : 0.f;                   \
                p2 = a4.z ? p2 : 0.f;  p3 = a4.w ? p3 : 0.f;                   \
                rs += (p0 + p1) + (p2 + p3);                                   \
                __half2 h01 = __floats2half2_rn(p0, p1);                       \
                __half2 h23 = __floats2half2_rn(p2, p3);                       \
                if (g == 0) { pk.x = *(unsigned*)&h01; pk.y = *(unsigned*)&h23; } \
                else        { pk.z = *(unsigned*)&h01; pk.w = *(unsigned*)&h23; } \
            }                                                                  \
            if (rep) rp1 += rs; else rp0 += rs;                                \
            *(uint4*)(pb + SWZ(row * 128 + c8 * 16)) = pk;                     \
        }                                                                      \
    } while (0)

    P_PHASE(0);
    av[0][0] = *(const int4*)(aj0 + 64);  av[0][1] = *(const int4*)(aj0 + 68);
    av[1][0] = *(const int4*)(aj1 + 64);  av[1][1] = *(const int4*)(aj1 + 68);

    float acc[8][2][4];
    #pragma unroll
    for (int i = 0; i < 8; ++i)
        #pragma unroll
        for (int m = 0; m < 2; ++m)
            #pragma unroll
            for (int c = 0; c < 4; ++c) acc[i][m][c] = 0.f;

    for (int tile = 0; tile < 32; ++tile) {
        __syncthreads();    // P(tile), H(tile) visible to all; buffer fences

        if (tile < 30) {    // H(tile+2), then ensure H(tile+1) landed
            int nt = tile + 2;
            unsigned hdst = sb + HS + (nt % 3) * 32768;
            const unsigned char* hsr = hsrc + (size_t)nt * 32768;
            #pragma unroll
            for (int q = 0; q < 4; ++q) {
                int idx = t + q * 512;
                CP16(hdst + idx * 16, hsr + idx * 16);
            }
            CPC();
            CPW1();
        } else {
            CPW0();
        }

        if (tile < 31) {
            P_PHASE(tile + 1);
            if (tile < 30) {            // LDG adj(tile+2) into regs
                int o = (tile + 2) * 64;
                av[0][0] = *(const int4*)(aj0 + o);  av[0][1] = *(const int4*)(aj0 + o + 4);
                av[1][0] = *(const int4*)(aj1 + o);  av[1][1] = *(const int4*)(aj1 + o + 4);
            }
        }

        // MMA(tile)
        unsigned pbase = sb + PS + (tile & 1) * 16384;
        unsigned hbase = sb + HS + (tile % 3) * 32768;
        #pragma unroll
        for (int ks = 0; ks < 4; ++ks) {
            unsigned a0[4], a1[4];
            LDSM4(a0[0], a0[1], a0[2], a0[3],
                  pbase + SWZ((wm * 32      + (l & 15)) * 128 + ks * 32 + (l >> 4) * 16));
            LDSM4(a1[0], a1[1], a1[2], a1[3],
                  pbase + SWZ((wm * 32 + 16 + (l & 15)) * 128 + ks * 32 + (l >> 4) * 16));
            #pragma unroll
            for (int nb2 = 0; nb2 < 4; ++nb2) {
                unsigned b0, b1, b2, b3;
                LDSM4(b0, b1, b2, b3,
                      hbase + SWZ((wn * 64 + nb2 * 16 + (l & 15)) * 128 + ks * 32 + (l >> 4) * 16));
                MMA(acc[2*nb2][0],   a0[0], a0[1], a0[2], a0[3], b0, b2);
                MMA(acc[2*nb2][1],   a1[0], a1[1], a1[2], a1[3], b0, b2);
                MMA(acc[2*nb2+1][0], a0[0], a0[1], a0[2], a0[3], b1, b3);
                MMA(acc[2*nb2+1][1], a1[0], a1[1], a1[2], a1[3], b1, b3);
            }
        }
    }

    // reduce row sums: 8 lanes (c8 = l&7) share each row
    rp0 += __shfl_xor_sync(0xFFFFFFFFu, rp0, 4);
    rp0 += __shfl_xor_sync(0xFFFFFFFFu, rp0, 2);
    rp0 += __shfl_xor_sync(0xFFFFFFFFu, rp0, 1);
    rp1 += __shfl_xor_sync(0xFFFFFFFFu, rp1, 4);
    rp1 += __shfl_xor_sync(0xFFFFFFFFu, rp1, 2);
    rp1 += __shfl_xor_sync(0xFFFFFFFFu, rp1, 1);
    __syncthreads();        // all MMA reads of P done before rsum reuse? (rsum separate) — order only
    if ((l & 7) == 0) {
        rsum[r0]      = rp0;
        rsum[r0 + 64] = rp1;
    }
    __syncthreads();

    #pragma unroll
    for (int mi = 0; mi < 2; ++mi) {
        int rr0 = wm * 32 + mi * 16 + (l >> 2);
        float s0 = rsum[rr0], s1 = rsum[rr0 + 8];
        float inv0 = (s0 > 0.f) ? 1.f / s0 : 0.f;
        float inv1 = (s1 > 0.f) ? 1.f / s1 : 0.f;
        float* o0 = out + ((size_t)b * N_ + i0 + rr0) * D_;
        float* o1 = o0 + 8 * D_;
        #pragma unroll
        for (int nb = 0; nb < 8; ++nb) {
            int c = wn * 64 + nb * 8 + 2 * (l & 3);
            *(float2*)(o0 + c) = make_float2(acc[nb][mi][0] * inv0,
                                             acc[nb][mi][1] * inv0);
            *(float2*)(o1 + c) = make_float2(acc[nb][mi][2] * inv1,
                                             acc[nb][mi][3] * inv1);
        }
    }
}

// ---------------------------------------------------------------------------
extern "C" void kernel_launch(void* const* d_in, const int* in_sizes, int n_in,
                              void* d_out, int out_size)
{
    const float* x   = (const float*)d_in[0];   // (8,2048,256) f32
    const int*   adj = (const int*)  d_in[1];   // (8,2048,2048) i32
    const float* W   = (const float*)d_in[2];   // (256,256) f32
    const float* a   = (const float*)d_in[3];   // (1,512) f32
    float*       out = (float*)d_out;           // (8,2048,256) f32

    cudaFuncSetAttribute(k_xh,   cudaFuncAttributeMaxDynamicSharedMemorySize, 98304);
    cudaFuncSetAttribute(k_aggr, cudaFuncAttributeMaxDynamicSharedMemorySize, 148992);

    k_wlr  <<<1, 256>>>(W, a);
    k_wconv<<<16, 256>>>(W);
    k_hlr  <<<(B_ * N_) / 8, 256>>>(x);
    k_xh   <<<dim3((B_ * N_) / 256, D_ / 64), 256, 98304>>>();
    k_aggr <<<dim3(N_ / 128, B_), 512, 148992>>>(adj, out);
}

// round 9
// speedup vs baseline: 1.0952x; 1.0952x over previous
#include <cuda_runtime.h>
#include <cuda_fp16.h>
#include <math.h>
#include <stdint.h>

#define B_ 8
#define N_ 2048
#define D_ 256

// ---------------------------------------------------------------------------
// helpers (baseline PTX only: cp.async / ldmatrix / mma.sync — compute_100 OK)
// ---------------------------------------------------------------------------
__device__ __forceinline__ unsigned smem_u32(const void* p) {
    unsigned a;
    asm("{ .reg .u64 t; cvta.to.shared.u64 t, %1; cvt.u32.u64 %0, t; }"
        : "=r"(a) : "l"(p));
    return a;
}
__device__ __forceinline__ int SWZ(int x) { return x ^ ((x >> 3) & 0x70); }

#define CP16(dst, src) \
    asm volatile("cp.async.cg.shared.global [%0], [%1], 16;" \
                 :: "r"((unsigned)(dst)), "l"(__cvta_generic_to_global(src)) : "memory")
#define CPC() asm volatile("cp.async.commit_group;" ::: "memory")
#define CPW0() asm volatile("cp.async.wait_group 0;" ::: "memory")
#define CPW1() asm volatile("cp.async.wait_group 1;" ::: "memory")

#define LDSM4(r0, r1, r2, r3, a) \
    asm volatile("ldmatrix.sync.aligned.m8n8.x4.shared.b16 {%0,%1,%2,%3}, [%4];" \
                 : "=r"(r0), "=r"(r1), "=r"(r2), "=r"(r3) : "r"((unsigned)(a)))

#define MMA(d, a0, a1, a2, a3, b0, b1) \
    asm volatile("mma.sync.aligned.m16n8k16.row.col.f32.f16.f16.f32 " \
                 "{%0,%1,%2,%3}, {%4,%5,%6,%7}, {%8,%9}, {%0,%1,%2,%3};" \
                 : "+f"((d)[0]), "+f"((d)[1]), "+f"((d)[2]), "+f"((d)[3]) \
                 : "r"(a0), "r"(a1), "r"(a2), "r"(a3), "r"(b0), "r"(b1))

// ---------------------------------------------------------------------------
// device globals (no allocation allowed)
// ---------------------------------------------------------------------------
__device__ float g_wl[D_];
__device__ float g_wr[D_];
__device__ __align__(16) float2 g_Elp[B_ * N_];   // (exp(hl), exp(0.2 hl))
__device__ __align__(16) float2 g_Erp[B_ * N_];   // (exp(hr), exp(0.2 hr))
__device__ __align__(16) __half g_Whf[D_ * D_];            // W fp16 row-major [o][k]
__device__ __align__(16) __half g_xh [B_ * N_ * D_];       // x fp16 row-major [m][k]
__device__ __align__(128) unsigned char g_ht[B_ * 32 * 32768]; // h^T fp16: [b][jt][d 256][j 64] swizzled

// ---------------- k_wlr: wl/wr vectors (1 block) ----------------------------
__global__ void k_wlr(const float* __restrict__ W, const float* __restrict__ a)
{
    int d = threadIdx.x;                      // 256 threads
    float sl = 0.f, sr = 0.f;
    #pragma unroll 8
    for (int o = 0; o < D_; ++o) {
        float w = W[o * D_ + d];
        sl = fmaf(a[o],      w, sl);
        sr = fmaf(a[D_ + o], w, sr);
    }
    g_wl[d] = sl;
    g_wr[d] = sr;
}

// ---------------- k_wconv: W f32 -> fp16, 16 blocks -------------------------
__global__ void k_wconv(const float* __restrict__ W)
{
    int i = blockIdx.x * 256 + threadIdx.x;   // 4096 threads, 16 f32 each
    const float4* W4 = (const float4*)W;
    __half2* o = (__half2*)g_Whf;
    #pragma unroll
    for (int q = 0; q < 4; ++q) {
        float4 v = W4[i * 4 + q];
        o[i * 8 + q * 2]     = __floats2half2_rn(v.x, v.y);
        o[i * 8 + q * 2 + 1] = __floats2half2_rn(v.z, v.w);
    }
}

// ---------------- k_hlr: hl/hr dots + factored exps + x->fp16 side-write ----
__global__ void k_hlr(const float* __restrict__ x)
{
    int m    = blockIdx.x * 8 + (threadIdx.x >> 5);
    int lane = threadIdx.x & 31;
    const float4* xr  = (const float4*)(x + (size_t)m * D_);
    const float4* wl4 = (const float4*)g_wl;
    const float4* wr4 = (const float4*)g_wr;
    float sl = 0.f, sr = 0.f;
    __half2* xo = (__half2*)(g_xh + (size_t)m * D_);
    #pragma unroll
    for (int q = 0; q < 2; ++q) {
        float4 xv = xr [lane + q * 32];
        float4 lv = wl4[lane + q * 32];
        float4 rv = wr4[lane + q * 32];
        sl += xv.x * lv.x + xv.y * lv.y + xv.z * lv.z + xv.w * lv.w;
        sr += xv.x * rv.x + xv.y * rv.y + xv.z * rv.z + xv.w * rv.w;
        xo[(lane + q * 32) * 2]     = __floats2half2_rn(xv.x, xv.y);
        xo[(lane + q * 32) * 2 + 1] = __floats2half2_rn(xv.z, xv.w);
    }
    #pragma unroll
    for (int off = 16; off > 0; off >>= 1) {
        sl += __shfl_xor_sync(0xFFFFFFFFu, sl, off);
        sr += __shfl_xor_sync(0xFFFFFFFFu, sr, off);
    }
    if (lane == 0) {
        g_Elp[m] = make_float2(expf(sl), expf(0.2f * sl));
        g_Erp[m] = make_float2(expf(sr), expf(0.2f * sr));
    }
}

// ---------------------------------------------------------------------------
// k_xh: h^T[d][j] = sum_k W[d][k] x[j][k]  (HMMA), smem-staged coalesced out
// CTA: 64 d x 256 j; warps m32 x n64; K loop 4 chunks of 64; 2 CTAs/SM
// ---------------------------------------------------------------------------
__global__ __launch_bounds__(256, 2) void k_xh()
{
    extern __shared__ char sm[];
    const int WS = 0, XS = 32768;
    unsigned sb = smem_u32(sm);
    int t = threadIdx.x, l = t & 31, w = t >> 5;
    int wm = w & 1, wn = w >> 1;
    int j0 = blockIdx.x * 256;
    int d0 = blockIdx.y * 64;

    #pragma unroll
    for (int q = 0; q < 8; ++q) {
        int idx = t + q * 256;
        int kc = idx >> 9, r = (idx >> 3) & 63, ch = idx & 7;
        CP16(sb + WS + kc * 8192 + SWZ(r * 128 + ch * 16),
             (const char*)g_Whf + (size_t)(d0 + r) * 512 + kc * 128 + ch * 16);
    }
    #pragma unroll
    for (int q = 0; q < 8; ++q) {
        int idx = t + q * 256, r = idx >> 3, ch = idx & 7;
        CP16(sb + XS + SWZ(r * 128 + ch * 16),
             (const char*)g_xh + (size_t)(j0 + r) * 512 + ch * 16);
    }
    CPC();

    float acc[8][2][4];
    #pragma unroll
    for (int i = 0; i < 8; ++i)
        #pragma unroll
        for (int m = 0; m < 2; ++m)
            #pragma unroll
            for (int c = 0; c < 4; ++c) acc[i][m][c] = 0.f;

    for (int kc = 0; kc < 4; ++kc) {
        if (kc < 3) {
            unsigned bbuf = sb + XS + ((kc + 1) & 1) * 32768;
            #pragma unroll
            for (int q = 0; q < 8; ++q) {
                int idx = t + q * 256, r = idx >> 3, ch = idx & 7;
                CP16(bbuf + SWZ(r * 128 + ch * 16),
                     (const char*)g_xh + (size_t)(j0 + r) * 512 + (kc + 1) * 128 + ch * 16);
            }
            CPC();
            CPW1();
        } else {
            CPW0();
        }
        __syncthreads();

        unsigned ab = sb + WS + kc * 8192;
        unsigned bb = sb + XS + (kc & 1) * 32768;
        #pragma unroll
        for (int ks = 0; ks < 4; ++ks) {
            unsigned a0[4], a1[4];
            LDSM4(a0[0], a0[1], a0[2], a0[3],
                  ab + SWZ((wm * 32      + (l & 15)) * 128 + ks * 32 + (l >> 4) * 16));
            LDSM4(a1[0], a1[1], a1[2], a1[3],
                  ab + SWZ((wm * 32 + 16 + (l & 15)) * 128 + ks * 32 + (l >> 4) * 16));
            #pragma unroll
            for (int nb2 = 0; nb2 < 4; ++nb2) {
                unsigned b0, b1, b2, b3;
                LDSM4(b0, b1, b2, b3,
                      bb + SWZ((wn * 64 + nb2 * 16 + (l & 15)) * 128 + ks * 32 + (l >> 4) * 16));
                MMA(acc[2*nb2][0],   a0[0], a0[1], a0[2], a0[3], b0, b2);
                MMA(acc[2*nb2][1],   a1[0], a1[1], a1[2], a1[3], b0, b2);
                MMA(acc[2*nb2+1][0], a0[0], a0[1], a0[2], a0[3], b1, b3);
                MMA(acc[2*nb2+1][1], a1[0], a1[1], a1[2], a1[3], b1, b3);
            }
        }
        __syncthreads();
    }

    // stage output (fp16, swizzled tile image) into smem, then coalesced copy
    #pragma unroll
    for (int mi = 0; mi < 2; ++mi) {
        int rd = wm * 32 + mi * 16 + (l >> 2);
        #pragma unroll
        for (int nb = 0; nb < 8; ++nb) {
            int jj = nb * 8 + 2 * (l & 3);
            __half2 v0 = __floats2half2_rn(acc[nb][mi][0], acc[nb][mi][1]);
            __half2 v1 = __floats2half2_rn(acc[nb][mi][2], acc[nb][mi][3]);
            *(__half2*)(sm + WS + wn * 8192 + SWZ( rd      * 128 + jj * 2)) = v0;
            *(__half2*)(sm + WS + wn * 8192 + SWZ((rd + 8) * 128 + jj * 2)) = v1;
        }
    }
    __syncthreads();

    int b   = j0 >> 11;
    int jt0 = (j0 & 2047) >> 6;
    #pragma unroll
    for (int q = 0; q < 8; ++q) {
        int c  = t + q * 256;                 // 2048 chunks x 16B
        int jt = c >> 9;
        int off = (c & 511) * 16;
        unsigned char* dst = g_ht + (size_t)(b * 32 + jt0 + jt) * 32768 + d0 * 128 + off;
        *(uint4*)dst = *(const uint4*)(sm + WS + c * 16);
    }
}

// ---------------------------------------------------------------------------
// k_aggr: fused masked-softmax aggregation (HMMA), depth-2 cp.async pipeline
// CTA 512 thr: i-tile M=128, warp tile m32 x n64 (wm, wn in 0..3), 32 j-tiles
// smem: H 3x32KB @0 | ADJ 2x32KB @98304 | P 2x16KB @163840 | ER 16KB @196608
//       | ELP 1KB @212992 | RSUM @214016   (total 214528)
// iter t: barrier -> issue G(t+2) -> MMA(t) -> wait(G(t+1)) -> P(t+1)
//   (the DRAM wait hides behind the tensor phase; adj copy/read is
//    self-paired per thread so per-thread wait_group visibility suffices)
// ---------------------------------------------------------------------------
__global__ __launch_bounds__(512) void k_aggr(const int* __restrict__ adj,
                                              float* __restrict__ out)
{
    extern __shared__ char sm[];
    const int HS = 0, AJ = 98304, PS = 163840, ERS = 196608;
    const int ELP = 212992, RSUM = 214016;
    unsigned sb = smem_u32(sm);
    int t = threadIdx.x, l = t & 31, w = t >> 5;
    int wm = w & 3, wn = w >> 2;
    int b = blockIdx.y, i0 = blockIdx.x * 128;
    float2* elp  = (float2*)(sm + ELP);
    float*  rsum = (float*)(sm + RSUM);

    const unsigned char* hsrc = g_ht + (size_t)b * 32 * 32768;
    const int*           adjb = adj + ((size_t)b * N_ + i0) * N_;

    // P(nt): p = adj ? max(El*Er, El2*Er2) : 0   (== exp(leaky(hl+hr)) masked)
    #define P_PHASE(nt) do {                                                     \
        char* pb = sm + PS + ((nt) & 1) * 16384;                                 \
        const int4*   aj4 = (const int4*)(sm + AJ + ((nt) & 1) * 32768);         \
        const float4* er4 = (const float4*)(sm + ERS);                           \
        _Pragma("unroll")                                                        \
        for (int rep = 0; rep < 4; ++rep) {                                      \
            int idx = t + rep * 512;                                             \
            int row = idx >> 4, c4 = idx & 15;                                   \
            int4 av = aj4[idx];                                                  \
            float2 el = elp[row];                                                \
            float4 ea = er4[(nt) * 32 + c4 * 2];                                 \
            float4 eb = er4[(nt) * 32 + c4 * 2 + 1];                             \
            float p0 = fmaxf(el.x * ea.x, el.y * ea.y);                          \
            float p1 = fmaxf(el.x * ea.z, el.y * ea.w);                          \
            float p2 = fmaxf(el.x * eb.x, el.y * eb.y);                          \
            float p3 = fmaxf(el.x * eb.z, el.y * eb.w);                          \
            p0 = av.x ? p0 : 0.f;  p1 = av.y ? p1 : 0.f;                         \
            p2 = av.z ? p2 : 0.f;  p3 = av.w ? p3 : 0.f;                         \
            __half2 h01 = __floats2half2_rn(p0, p1);                             \
            __half2 h23 = __floats2half2_rn(p2, p3);                             \
            uint2 pk;                                                            \
            pk.x = *(unsigned*)&h01;                                             \
            pk.y = *(unsigned*)&h23;                                             \
            *(uint2*)(pb + SWZ(row * 128 + c4 * 8)) = pk;                        \
        }                                                                        \
    } while (0)

    // G0: H(0) + ADJ(0) + Er row + Elp
    #pragma unroll
    for (int q = 0; q < 4; ++q) {
        int idx = t + q * 512;
        CP16(sb + HS + idx * 16, hsrc + idx * 16);
    }
    #pragma unroll
    for (int q = 0; q < 4; ++q) {
        int idx = t + q * 512;
        CP16(sb + AJ + idx * 16, adjb + ((size_t)(idx >> 4)) * N_ + (idx & 15) * 4);
    }
    #pragma unroll
    for (int q = 0; q < 2; ++q) {
        int idx = t + q * 512;
        CP16(sb + ERS + idx * 16, (const char*)(g_Erp + b * N_) + idx * 16);
    }
    if (t < 64) CP16(sb + ELP + t * 16, (const char*)(g_Elp + b * N_ + i0) + t * 16);
    CPC();
    // G1: H(1) + ADJ(1)
    #pragma unroll
    for (int q = 0; q < 4; ++q) {
        int idx = t + q * 512;
        CP16(sb + HS + 32768 + idx * 16, hsrc + 32768 + idx * 16);
    }
    #pragma unroll
    for (int q = 0; q < 4; ++q) {
        int idx = t + q * 512;
        CP16(sb + AJ + 32768 + idx * 16,
             adjb + 64 + ((size_t)(idx >> 4)) * N_ + (idx & 15) * 4);
    }
    CPC();
    CPW1();                 // G0 arrived (G1 in flight)
    __syncthreads();

    P_PHASE(0);             // overlaps G1 flight

    float acc[8][2][4];
    #pragma unroll
    for (int i = 0; i < 8; ++i)
        #pragma unroll
        for (int m = 0; m < 2; ++m)
            #pragma unroll
            for (int c = 0; c < 4; ++c) acc[i][m][c] = 0.f;
    float sacc[2][4] = {{0.f,0.f,0.f,0.f},{0.f,0.f,0.f,0.f}};
    const unsigned ONESH = 0x3C003C00u;

    for (int tile = 0; tile < 32; ++tile) {
        __syncthreads();    // P(tile) + H(tile) visible; buffer-reuse fence

        if (tile < 30) {    // issue G(tile+2)
            int nt = tile + 2;
            unsigned hdst = sb + HS + (nt % 3) * 32768;
            unsigned adst = sb + AJ + (nt & 1) * 32768;
            const unsigned char* hsr = hsrc + (size_t)nt * 32768;
            const int*           asr = adjb + nt * 64;
            #pragma unroll
            for (int q = 0; q < 4; ++q) {
                int idx = t + q * 512;
                CP16(hdst + idx * 16, hsr + idx * 16);
            }
            #pragma unroll
            for (int q = 0; q < 4; ++q) {
                int idx = t + q * 512;
                CP16(adst + idx * 16, asr + ((size_t)(idx >> 4)) * N_ + (idx & 15) * 4);
            }
            CPC();
        }

        // MMA(tile) — runs while G(tile+1) may still be landing
        unsigned pbase = sb + PS + (tile & 1) * 16384;
        unsigned hbase = sb + HS + (tile % 3) * 32768;
        #pragma unroll
        for (int ks = 0; ks < 4; ++ks) {
            unsigned a0[4], a1[4];
            LDSM4(a0[0], a0[1], a0[2], a0[3],
                  pbase + SWZ((wm * 32      + (l & 15)) * 128 + ks * 32 + (l >> 4) * 16));
            LDSM4(a1[0], a1[1], a1[2], a1[3],
                  pbase + SWZ((wm * 32 + 16 + (l & 15)) * 128 + ks * 32 + (l >> 4) * 16));
            if (wn == 0) {
                MMA(sacc[0], a0[0], a0[1], a0[2], a0[3], ONESH, ONESH);
                MMA(sacc[1], a1[0], a1[1], a1[2], a1[3], ONESH, ONESH);
            }
            #pragma unroll
            for (int nb2 = 0; nb2 < 4; ++nb2) {
                unsigned b0, b1, b2, b3;
                LDSM4(b0, b1, b2, b3,
                      hbase + SWZ((wn * 64 + nb2 * 16 + (l & 15)) * 128 + ks * 32 + (l >> 4) * 16));
                MMA(acc[2*nb2][0],   a0[0], a0[1], a0[2], a0[3], b0, b2);
                MMA(acc[2*nb2][1],   a1[0], a1[1], a1[2], a1[3], b0, b2);
                MMA(acc[2*nb2+1][0], a0[0], a0[1], a0[2], a0[3], b1, b3);
                MMA(acc[2*nb2+1][1], a1[0], a1[1], a1[2], a1[3], b1, b3);
            }
        }

        // wait for G(tile+1) (adj self-paired per thread), then build P(tile+1)
        if (tile < 30) CPW1(); else CPW0();
        if (tile < 31) P_PHASE(tile + 1);
    }

    __syncthreads();
    if (wn == 0 && (l & 3) == 0) {
        int r = wm * 32 + (l >> 2);
        rsum[r]      = sacc[0][0];
        rsum[r + 8]  = sacc[0][2];
        rsum[r + 16] = sacc[1][0];
        rsum[r + 24] = sacc[1][2];
    }
    __syncthreads();

    #pragma unroll
    for (int mi = 0; mi < 2; ++mi) {
        int r0 = wm * 32 + mi * 16 + (l >> 2);
        float s0 = rsum[r0], s1 = rsum[r0 + 8];
        float inv0 = (s0 > 0.f) ? 1.f / s0 : 0.f;
        float inv1 = (s1 > 0.f) ? 1.f / s1 : 0.f;
        float* o0 = out + ((size_t)b * N_ + i0 + r0) * D_;
        float* o1 = o0 + 8 * D_;
        #pragma unroll
        for (int nb = 0; nb < 8; ++nb) {
            int c = wn * 64 + nb * 8 + 2 * (l & 3);
            *(float2*)(o0 + c) = make_float2(acc[nb][mi][0] * inv0,
                                             acc[nb][mi][1] * inv0);
            *(float2*)(o1 + c) = make_float2(acc[nb][mi][2] * inv1,
                                             acc[nb][mi][3] * inv1);
        }
    }
}

// ---------------------------------------------------------------------------
extern "C" void kernel_launch(void* const* d_in, const int* in_sizes, int n_in,
                              void* d_out, int out_size)
{
    const float* x   = (const float*)d_in[0];   // (8,2048,256) f32
    const int*   adj = (const int*)  d_in[1];   // (8,2048,2048) i32
    const float* W   = (const float*)d_in[2];   // (256,256) f32
    const float* a   = (const float*)d_in[3];   // (1,512) f32
    float*       out = (float*)d_out;           // (8,2048,256) f32

    cudaFuncSetAttribute(k_xh,   cudaFuncAttributeMaxDynamicSharedMemorySize, 98304);
    cudaFuncSetAttribute(k_aggr, cudaFuncAttributeMaxDynamicSharedMemorySize, 214528);

    k_wlr  <<<1, 256>>>(W, a);
    k_wconv<<<16, 256>>>(W);
    k_hlr  <<<(B_ * N_) / 8, 256>>>(x);
    k_xh   <<<dim3((B_ * N_) / 256, D_ / 64), 256, 98304>>>();
    k_aggr <<<dim3(N_ / 128, B_), 512, 214528>>>(adj, out);
}